// round 5
// baseline (speedup 1.0000x reference)
#include <cuda_runtime.h>
#include <cuda_bf16.h>
#include <math.h>

// GCN 4-layer, pull-based CSR, fused transforms, bf16 rows, 4-edges-per-
// iteration wide pull (8-lane groups x uint2), layer-1 scalar aggregation
// pushed during CSR fill.

#define MAXN 100000
#define MAXE 3200000
#define SCAN_B 256
#define MAX_BLKS 512

__device__ int   g_cnt[MAXN];           // zero at entry (re-zeroed in k_l1)
__device__ int   g_rowpart[MAXN];
__device__ int   g_bsum[MAX_BLKS];
__device__ int   g_rows[MAXN + 1];
__device__ int   g_cursor[MAXN];
__device__ int   g_adj[MAXE];
__device__ float g_dinv[MAXN];
__device__ float g_xs[MAXN];            // dinv[i]*x[i]
__device__ float g_s[MAXN];             // layer-1 scalar aggregate (zero at entry)
__device__ float g_t[MAXN];             // layer-4 scalar feature
__device__ uint2 g_HtA[MAXN * 8];       // 32 bf16 channels per node (64B row)
__device__ uint2 g_HtB[MAXN * 8];

__global__ void k_hist(const int* __restrict__ dst, int e) {
    int i = blockIdx.x * blockDim.x + threadIdx.x;
    if (i < e) atomicAdd(&g_cnt[__ldg(dst + i)], 1);
}

__global__ void k_scan1(int n) {
    __shared__ int wsum[8];
    int tid = threadIdx.x, lane = tid & 31, w = tid >> 5;
    int i = blockIdx.x * SCAN_B + tid;
    int v = (i < n) ? g_cnt[i] : 0;
    int s = v;
#pragma unroll
    for (int o = 1; o < 32; o <<= 1) {
        int t = __shfl_up_sync(0xffffffffu, s, o);
        if (lane >= o) s += t;
    }
    if (lane == 31) wsum[w] = s;
    __syncthreads();
    if (w == 0 && lane < 8) {
        int ws = wsum[lane];
#pragma unroll
        for (int o = 1; o < 8; o <<= 1) {
            int t = __shfl_up_sync(0x000000ffu, ws, o);
            if (lane >= o) ws += t;
        }
        wsum[lane] = ws;
    }
    __syncthreads();
    int off = (w > 0) ? wsum[w - 1] : 0;
    if (i < n) g_rowpart[i] = off + s - v;
    if (tid == SCAN_B - 1) g_bsum[blockIdx.x] = off + s;
}

__global__ void k_scan2(int nb) {
    __shared__ int wsum[16];
    int tid = threadIdx.x, lane = tid & 31, w = tid >> 5;
    int v = (tid < nb) ? g_bsum[tid] : 0;
    int s = v;
#pragma unroll
    for (int o = 1; o < 32; o <<= 1) {
        int t = __shfl_up_sync(0xffffffffu, s, o);
        if (lane >= o) s += t;
    }
    if (lane == 31) wsum[w] = s;
    __syncthreads();
    if (w == 0) {
        int ws = (lane < 16) ? wsum[lane] : 0;
#pragma unroll
        for (int o = 1; o < 16; o <<= 1) {
            int t = __shfl_up_sync(0xffffffffu, ws, o);
            if (lane >= o) ws += t;
        }
        if (lane < 16) wsum[lane] = ws;
    }
    __syncthreads();
    int off = (w > 0) ? wsum[w - 1] : 0;
    if (tid < nb) g_bsum[tid] = off + s - v;
}

__global__ void k_scan3(const float* __restrict__ x, int n, int e) {
    int i = blockIdx.x * blockDim.x + threadIdx.x;
    if (i >= n) return;
    int rs = g_rowpart[i] + g_bsum[i / SCAN_B];
    g_rows[i] = rs;
    g_cursor[i] = rs;
    if (i == 0) g_rows[n] = e;
    float di = rsqrtf((float)g_cnt[i] + 1.0f);
    g_dinv[i] = di;
    g_xs[i] = di * __ldg(x + i);
}

// CSR fill + layer-1 scalar push fused.
__global__ void k_fill(const int* __restrict__ src, const int* __restrict__ dst, int e) {
    int i = blockIdx.x * blockDim.x + threadIdx.x;
    if (i >= e) return;
    int s = __ldg(src + i);
    int d = __ldg(dst + i);
    int pos = atomicAdd(&g_cursor[d], 1);
    g_adj[pos] = s;
    atomicAdd(&g_s[d], __ldg(&g_xs[s]));
}

// Layer 1 (node-parallel now): expand scalar -> W_mid transform -> HtA.
__global__ void k_l1(const float* __restrict__ Win, const float* __restrict__ bin,
                     const float* __restrict__ Wmid, int n) {
    __shared__ float sW[1024];
    for (int k = threadIdx.x; k < 1024; k += blockDim.x) sW[k] = Wmid[k];
    __syncthreads();
    int gt = blockIdx.x * blockDim.x + threadIdx.x;
    int i = gt >> 5, lane = gt & 31;
    if (i >= n) return;
    float sv = 0.0f;
    if (lane == 0) { sv = g_s[i]; g_s[i] = 0.0f; g_cnt[i] = 0; }  // read + replay re-zero
    sv = __shfl_sync(0xffffffffu, sv, 0);
    float di = g_dinv[i];
    float tot = di * (sv + g_xs[i]);
    float hv = fmaxf(fmaf(tot, __ldg(Win + lane), __ldg(bin + lane)), 0.0f);
    float acc = 0.0f;
#pragma unroll
    for (int k = 0; k < 32; k++) {
        float hk = __shfl_sync(0xffffffffu, hv, k);
        acc = fmaf(hk, sW[k * 32 + lane], acc);
    }
    ((__nv_bfloat16*)g_HtA)[i * 32 + lane] = __float2bfloat16(di * acc);
}

// Wide pull: 4 edges/iteration. 8-lane groups, each lane loads uint2 (4 bf16 ch).
__device__ __forceinline__ float wide_pull(const uint2* __restrict__ Hb, int i, int lane) {
    int rs = g_rows[i];
    int deg = g_rows[i + 1] - rs;
    int grp = lane >> 3;          // 0..3: which edge of the quad
    int cl  = lane & 7;           // 8B chunk index (channels 4cl..4cl+3)
    float a0 = 0.f, a1 = 0.f, a2 = 0.f, a3 = 0.f;
    int base = 0;
    for (; base + 32 <= deg; base += 32) {
        int eidx = __ldg(&g_adj[rs + base + lane]);
#pragma unroll
        for (int k = 0; k < 8; k++) {
            int sidx = __shfl_sync(0xffffffffu, eidx, 4 * k + grp);
            uint2 u = __ldg(&Hb[sidx * 8 + cl]);
            float2 f0 = __bfloat1622float2(*(__nv_bfloat162*)&u.x);
            float2 f1 = __bfloat1622float2(*(__nv_bfloat162*)&u.y);
            a0 += f0.x; a1 += f0.y; a2 += f1.x; a3 += f1.y;
        }
    }
    int rem = deg - base;
    if (rem > 0) {
        int eidx = (lane < rem) ? __ldg(&g_adj[rs + base + lane]) : 0;
        int iters = (rem + 3) >> 2;
        for (int k = 0; k < iters; k++) {
            int eoff = 4 * k + grp;
            int sidx = __shfl_sync(0xffffffffu, eidx, eoff);
            if (eoff < rem) {
                uint2 u = __ldg(&Hb[sidx * 8 + cl]);
                float2 f0 = __bfloat1622float2(*(__nv_bfloat162*)&u.x);
                float2 f1 = __bfloat1622float2(*(__nv_bfloat162*)&u.y);
                a0 += f0.x; a1 += f0.y; a2 += f1.x; a3 += f1.y;
            }
        }
    }
    // combine the 4 groups
    a0 += __shfl_xor_sync(0xffffffffu, a0, 8);
    a1 += __shfl_xor_sync(0xffffffffu, a1, 8);
    a2 += __shfl_xor_sync(0xffffffffu, a2, 8);
    a3 += __shfl_xor_sync(0xffffffffu, a3, 8);
    a0 += __shfl_xor_sync(0xffffffffu, a0, 16);
    a1 += __shfl_xor_sync(0xffffffffu, a1, 16);
    a2 += __shfl_xor_sync(0xffffffffu, a2, 16);
    a3 += __shfl_xor_sync(0xffffffffu, a3, 16);
    // self term (values now replicated across groups; add to each copy)
    {
        uint2 u = __ldg(&Hb[i * 8 + cl]);
        float2 f0 = __bfloat1622float2(*(__nv_bfloat162*)&u.x);
        float2 f1 = __bfloat1622float2(*(__nv_bfloat162*)&u.y);
        a0 += f0.x; a1 += f0.y; a2 += f1.x; a3 += f1.y;
    }
    // redistribute: channel c=lane lives in chunk c>>2 (source lane c>>2), comp c&3
    int srcl = lane >> 2;
    float v0 = __shfl_sync(0xffffffffu, a0, srcl);
    float v1 = __shfl_sync(0xffffffffu, a1, srcl);
    float v2 = __shfl_sync(0xffffffffu, a2, srcl);
    float v3 = __shfl_sync(0xffffffffu, a3, srcl);
    int c = lane & 3;
    return (c == 0) ? v0 : (c == 1) ? v1 : (c == 2) ? v2 : v3;
}

// Layer 2: wide pull HtA -> relu -> W_mid transform -> HtB.
__global__ void k_pull2(const float* __restrict__ bmid, const float* __restrict__ Wmid, int n) {
    __shared__ float sW[1024];
    for (int k = threadIdx.x; k < 1024; k += blockDim.x) sW[k] = Wmid[k];
    __syncthreads();
    int gt = blockIdx.x * blockDim.x + threadIdx.x;
    int i = gt >> 5, lane = gt & 31;
    if (i >= n) return;
    float aggr = wide_pull(g_HtA, i, lane);
    float di = g_dinv[i];
    float hv = fmaxf(fmaf(di, aggr, __ldg(bmid + lane)), 0.0f);
    float acc = 0.0f;
#pragma unroll
    for (int k = 0; k < 32; k++) {
        float hk = __shfl_sync(0xffffffffu, hv, k);
        acc = fmaf(hk, sW[k * 32 + lane], acc);
    }
    ((__nv_bfloat16*)g_HtB)[i * 32 + lane] = __float2bfloat16(di * acc);
}

// Layer 3: wide pull HtB -> relu -> dot W_out -> scalar t.
__global__ void k_pull3(const float* __restrict__ bmid, const float* __restrict__ Wout, int n) {
    int gt = blockIdx.x * blockDim.x + threadIdx.x;
    int i = gt >> 5, lane = gt & 31;
    if (i >= n) return;
    float aggr = wide_pull(g_HtB, i, lane);
    float di = g_dinv[i];
    float hv = fmaxf(fmaf(di, aggr, __ldg(bmid + lane)), 0.0f);
    float v = hv * __ldg(Wout + lane);
#pragma unroll
    for (int o = 16; o; o >>= 1) v += __shfl_xor_sync(0xffffffffu, v, o);
    if (lane == 0) g_t[i] = di * v;
}

// Layer 4: scalar pull + sigmoid.
__global__ void k_out(const float* __restrict__ bout, float* __restrict__ out, int n) {
    int gt = blockIdx.x * blockDim.x + threadIdx.x;
    int i = gt >> 5, lane = gt & 31;
    if (i >= n) return;
    int rs = g_rows[i];
    int deg = g_rows[i + 1] - rs;
    float s = 0.0f;
    int base = 0;
    for (; base + 32 <= deg; base += 32)
        s += __ldg(&g_t[__ldg(&g_adj[rs + base + lane])]);
    if (base + lane < deg)
        s += __ldg(&g_t[__ldg(&g_adj[rs + base + lane])]);
#pragma unroll
    for (int o = 16; o; o >>= 1) s += __shfl_xor_sync(0xffffffffu, s, o);
    if (lane == 0) {
        float v = g_dinv[i] * (s + g_t[i]) + __ldg(bout);
        out[i] = 1.0f / (1.0f + expf(-v));
    }
}

extern "C" void kernel_launch(void* const* d_in, const int* in_sizes, int n_in,
                              void* d_out, int out_size) {
    const float* x    = (const float*)d_in[0];
    const int*   ei   = (const int*)  d_in[1];
    const float* Win  = (const float*)d_in[2];
    const float* bin  = (const float*)d_in[3];
    const float* Wmid = (const float*)d_in[4];
    const float* bmid = (const float*)d_in[5];
    const float* Wout = (const float*)d_in[6];
    const float* bout = (const float*)d_in[7];

    int n = in_sizes[0];
    int e = in_sizes[1] / 2;
    const int* src = ei;
    const int* dst = ei + e;

    const int B = 256;
    int gN   = (n + B - 1) / B;
    int gN32 = (n * 32 + B - 1) / B;
    int gE   = (e + B - 1) / B;

    // CSR build + layer-1 scalar push
    k_hist<<<gE, B>>>(dst, e);
    k_scan1<<<gN, SCAN_B>>>(n);
    k_scan2<<<1, 512>>>(gN);
    k_scan3<<<gN, B>>>(x, n, e);
    k_fill<<<gE, B>>>(src, dst, e);

    // fused layers
    k_l1<<<gN32, B>>>(Win, bin, Wmid, n);
    k_pull2<<<gN32, B>>>(bmid, Wmid, n);
    k_pull3<<<gN32, B>>>(bmid, Wout, n);
    k_out<<<gN32, B>>>(bout, (float*)d_out, n);
}

// round 6
// speedup vs baseline: 1.1471x; 1.1471x over previous
#include <cuda_runtime.h>
#include <cuda_bf16.h>
#include <math.h>

// GCN 4-layer, pull-based CSR, fused transforms, bf16 feature rows,
// 2-edges-per-iteration wide pull; full 32-edge batches specialized with
// unrolled, unpredicated inner loop for high MLP.

#define MAXN 100000
#define MAXE 3200000
#define SCAN_B 256
#define MAX_BLKS 512

__device__ int   g_cnt[MAXN];           // zero at entry (re-zeroed in k_l1)
__device__ int   g_rowpart[MAXN];
__device__ int   g_bsum[MAX_BLKS];
__device__ int   g_rows[MAXN + 1];
__device__ int   g_cursor[MAXN];
__device__ int   g_adj[MAXE];
__device__ float g_dinv[MAXN];
__device__ float g_xs[MAXN];            // dinv[i]*x[i]
__device__ float g_t[MAXN];             // layer-4 scalar feature
__device__ __nv_bfloat162 g_HtA[MAXN * 16];   // 32 bf16 channels / node
__device__ __nv_bfloat162 g_HtB[MAXN * 16];

__global__ void k_hist(const int* __restrict__ dst, int e) {
    int i = blockIdx.x * blockDim.x + threadIdx.x;
    if (i < e) atomicAdd(&g_cnt[__ldg(dst + i)], 1);
}

__global__ void k_scan1(int n) {
    __shared__ int wsum[8];
    int tid = threadIdx.x, lane = tid & 31, w = tid >> 5;
    int i = blockIdx.x * SCAN_B + tid;
    int v = (i < n) ? g_cnt[i] : 0;
    int s = v;
#pragma unroll
    for (int o = 1; o < 32; o <<= 1) {
        int t = __shfl_up_sync(0xffffffffu, s, o);
        if (lane >= o) s += t;
    }
    if (lane == 31) wsum[w] = s;
    __syncthreads();
    if (w == 0 && lane < 8) {
        int ws = wsum[lane];
#pragma unroll
        for (int o = 1; o < 8; o <<= 1) {
            int t = __shfl_up_sync(0x000000ffu, ws, o);
            if (lane >= o) ws += t;
        }
        wsum[lane] = ws;
    }
    __syncthreads();
    int off = (w > 0) ? wsum[w - 1] : 0;
    if (i < n) g_rowpart[i] = off + s - v;
    if (tid == SCAN_B - 1) g_bsum[blockIdx.x] = off + s;
}

__global__ void k_scan2(int nb) {
    __shared__ int wsum[16];
    int tid = threadIdx.x, lane = tid & 31, w = tid >> 5;
    int v = (tid < nb) ? g_bsum[tid] : 0;
    int s = v;
#pragma unroll
    for (int o = 1; o < 32; o <<= 1) {
        int t = __shfl_up_sync(0xffffffffu, s, o);
        if (lane >= o) s += t;
    }
    if (lane == 31) wsum[w] = s;
    __syncthreads();
    if (w == 0) {
        int ws = (lane < 16) ? wsum[lane] : 0;
#pragma unroll
        for (int o = 1; o < 16; o <<= 1) {
            int t = __shfl_up_sync(0xffffffffu, ws, o);
            if (lane >= o) ws += t;
        }
        if (lane < 16) wsum[lane] = ws;
    }
    __syncthreads();
    int off = (w > 0) ? wsum[w - 1] : 0;
    if (tid < nb) g_bsum[tid] = off + s - v;
}

__global__ void k_scan3(const float* __restrict__ x, int n, int e) {
    int i = blockIdx.x * blockDim.x + threadIdx.x;
    if (i >= n) return;
    int rs = g_rowpart[i] + g_bsum[i / SCAN_B];
    g_rows[i] = rs;
    g_cursor[i] = rs;
    if (i == 0) g_rows[n] = e;
    float di = rsqrtf((float)g_cnt[i] + 1.0f);
    g_dinv[i] = di;
    g_xs[i] = di * __ldg(x + i);
}

__global__ void k_fill(const int* __restrict__ src, const int* __restrict__ dst, int e) {
    int i = blockIdx.x * blockDim.x + threadIdx.x;
    if (i >= e) return;
    int pos = atomicAdd(&g_cursor[__ldg(dst + i)], 1);
    g_adj[pos] = __ldg(src + i);
}

// Layer 1: scalar pull -> expand -> W_mid transform -> HtA (bf16).
__global__ void k_l1(const float* __restrict__ Win, const float* __restrict__ bin,
                     const float* __restrict__ Wmid, int n) {
    __shared__ float sW[1024];
    for (int k = threadIdx.x; k < 1024; k += blockDim.x) sW[k] = Wmid[k];
    __syncthreads();
    int gt = blockIdx.x * blockDim.x + threadIdx.x;
    int i = gt >> 5, lane = gt & 31;
    if (i >= n) return;
    int rs = g_rows[i];
    int deg = g_rows[i + 1] - rs;
    if (lane == 1) g_cnt[i] = 0;                    // re-zero for next replay
    float s = 0.0f;
    for (int j = lane; j < deg; j += 32)
        s += __ldg(&g_xs[__ldg(&g_adj[rs + j])]);
#pragma unroll
    for (int o = 16; o; o >>= 1) s += __shfl_xor_sync(0xffffffffu, s, o);
    float di = g_dinv[i];
    float tot = di * (s + g_xs[i]);
    float hv = fmaxf(fmaf(tot, __ldg(Win + lane), __ldg(bin + lane)), 0.0f);
    float acc = 0.0f;
#pragma unroll
    for (int k = 0; k < 32; k++) {
        float hk = __shfl_sync(0xffffffffu, hv, k);
        acc = fmaf(hk, sW[k * 32 + lane], acc);
    }
    ((__nv_bfloat16*)g_HtA)[i * 32 + lane] = __float2bfloat16(di * acc);
}

// Wide pull core: per-lane channel value of (sum_nbr + self) on bf16 rows.
// 2 edges/iteration (16-lane groups, bf16x2 per lane). Full 32-edge batches
// take an unrolled unpredicated path (16 independent gathers -> high MLP).
__device__ __forceinline__ float wide_pull(const __nv_bfloat162* __restrict__ Hb,
                                           int i, int lane) {
    int rs = g_rows[i];
    int deg = g_rows[i + 1] - rs;
    int grp = lane >> 4;          // 0/1: which edge of the pair
    int cl  = lane & 15;          // channel-pair index
    // self term first (overlaps with loop latency)
    float2 fs = __bfloat1622float2(__ldg(&Hb[i * 16 + cl]));
    float ax = fs.x * 0.5f, ay = fs.y * 0.5f;  // halved: added once per group copy
    int base = 0;
    for (; base + 32 <= deg; base += 32) {
        int eidx = __ldg(&g_adj[rs + base + lane]);
#pragma unroll
        for (int k = 0; k < 16; k++) {
            int sidx = __shfl_sync(0xffffffffu, eidx, 2 * k + grp);
            float2 f = __bfloat1622float2(__ldg(&Hb[sidx * 16 + cl]));
            ax += f.x; ay += f.y;
        }
    }
    int rem = deg - base;
    if (rem > 0) {
        int eidx = (lane < rem) ? __ldg(&g_adj[rs + base + lane]) : 0;
        int half = (rem + 1) >> 1;
        for (int k = 0; k < half; k++) {
            int eoff = 2 * k + grp;
            int sidx = __shfl_sync(0xffffffffu, eidx, eoff);
            if (eoff < rem) {
                float2 f = __bfloat1622float2(__ldg(&Hb[sidx * 16 + cl]));
                ax += f.x; ay += f.y;
            }
        }
    }
    ax += __shfl_xor_sync(0xffffffffu, ax, 16);
    ay += __shfl_xor_sync(0xffffffffu, ay, 16);
    // redistribute: channel c=lane lives at lane c>>1, component c&1
    float vx = __shfl_sync(0xffffffffu, ax, lane >> 1);
    float vy = __shfl_sync(0xffffffffu, ay, lane >> 1);
    return (lane & 1) ? vy : vx;
}

// Layer 2: wide pull HtA -> relu -> W_mid transform -> HtB (bf16).
__global__ void k_pull2(const float* __restrict__ bmid, const float* __restrict__ Wmid, int n) {
    __shared__ float sW[1024];
    for (int k = threadIdx.x; k < 1024; k += blockDim.x) sW[k] = Wmid[k];
    __syncthreads();
    int gt = blockIdx.x * blockDim.x + threadIdx.x;
    int i = gt >> 5, lane = gt & 31;
    if (i >= n) return;
    float aggr = wide_pull(g_HtA, i, lane);
    float di = g_dinv[i];
    float hv = fmaxf(fmaf(di, aggr, __ldg(bmid + lane)), 0.0f);
    float acc = 0.0f;
#pragma unroll
    for (int k = 0; k < 32; k++) {
        float hk = __shfl_sync(0xffffffffu, hv, k);
        acc = fmaf(hk, sW[k * 32 + lane], acc);
    }
    ((__nv_bfloat16*)g_HtB)[i * 32 + lane] = __float2bfloat16(di * acc);
}

// Layer 3: wide pull HtB -> relu -> dot W_out -> scalar t.
__global__ void k_pull3(const float* __restrict__ bmid, const float* __restrict__ Wout, int n) {
    int gt = blockIdx.x * blockDim.x + threadIdx.x;
    int i = gt >> 5, lane = gt & 31;
    if (i >= n) return;
    float aggr = wide_pull(g_HtB, i, lane);
    float di = g_dinv[i];
    float hv = fmaxf(fmaf(di, aggr, __ldg(bmid + lane)), 0.0f);
    float v = hv * __ldg(Wout + lane);
#pragma unroll
    for (int o = 16; o; o >>= 1) v += __shfl_xor_sync(0xffffffffu, v, o);
    if (lane == 0) g_t[i] = di * v;
}

// Layer 4: scalar pull + sigmoid.
__global__ void k_out(const float* __restrict__ bout, float* __restrict__ out, int n) {
    int gt = blockIdx.x * blockDim.x + threadIdx.x;
    int i = gt >> 5, lane = gt & 31;
    if (i >= n) return;
    int rs = g_rows[i];
    int deg = g_rows[i + 1] - rs;
    float s = 0.0f;
    int base = 0;
    for (; base + 32 <= deg; base += 32)
        s += __ldg(&g_t[__ldg(&g_adj[rs + base + lane])]);
    if (base + lane < deg)
        s += __ldg(&g_t[__ldg(&g_adj[rs + base + lane])]);
#pragma unroll
    for (int o = 16; o; o >>= 1) s += __shfl_xor_sync(0xffffffffu, s, o);
    if (lane == 0) {
        float v = g_dinv[i] * (s + g_t[i]) + __ldg(bout);
        out[i] = 1.0f / (1.0f + expf(-v));
    }
}

extern "C" void kernel_launch(void* const* d_in, const int* in_sizes, int n_in,
                              void* d_out, int out_size) {
    const float* x    = (const float*)d_in[0];
    const int*   ei   = (const int*)  d_in[1];
    const float* Win  = (const float*)d_in[2];
    const float* bin  = (const float*)d_in[3];
    const float* Wmid = (const float*)d_in[4];
    const float* bmid = (const float*)d_in[5];
    const float* Wout = (const float*)d_in[6];
    const float* bout = (const float*)d_in[7];

    int n = in_sizes[0];
    int e = in_sizes[1] / 2;
    const int* src = ei;
    const int* dst = ei + e;

    const int B = 256;
    int gN   = (n + B - 1) / B;
    int gN32 = (n * 32 + B - 1) / B;
    int gE   = (e + B - 1) / B;

    // CSR build
    k_hist<<<gE, B>>>(dst, e);
    k_scan1<<<gN, SCAN_B>>>(n);
    k_scan2<<<1, 512>>>(gN);
    k_scan3<<<gN, B>>>(x, n, e);
    k_fill<<<gE, B>>>(src, dst, e);

    // fused layers
    k_l1<<<gN32, B>>>(Win, bin, Wmid, n);
    k_pull2<<<gN32, B>>>(bmid, Wmid, n);
    k_pull3<<<gN32, B>>>(bmid, Wout, n);
    k_out<<<gN32, B>>>(bout, (float*)d_out, n);
}